// round 11
// baseline (speedup 1.0000x reference)
#include <cuda_runtime.h>
#include <cstdint>
#include <stdint.h>
#include <mma.h>

using namespace nvcuda;

#define HIDN 1024
#define NH   16
#define HD   64
#define ROTD 32
#define NB   2
#define SQ   2048
#define MTOT (NB*SQ)   // 4096 tokens

// Scratch (device globals; no allocation allowed)
__device__ float g_q [MTOT*HIDN];
__device__ float g_k [MTOT*HIDN];
__device__ float g_v [MTOT*HIDN];
__device__ float g_ao[MTOT*HIDN];

// ---------------------------------------------------------------------------
// cp.async helpers (LDGSTS, 16B)
// ---------------------------------------------------------------------------
__device__ __forceinline__ void cpa16(void* smem_dst, const void* gmem_src) {
    unsigned d = (unsigned)__cvta_generic_to_shared(smem_dst);
    asm volatile("cp.async.cg.shared.global [%0], [%1], 16;" :: "r"(d), "l"(gmem_src));
}
__device__ __forceinline__ void cpa_commit() {
    asm volatile("cp.async.commit_group;");
}
template <int N>
__device__ __forceinline__ void cpa_wait() {
    asm volatile("cp.async.wait_group %0;" :: "n"(N));
}

// ---------------------------------------------------------------------------
// 3xTF32 split: hi = tf32(a), lo = tf32(a - hi).  A@B ~= AhBh + AhBl + AlBh.
// Per-product error ~2^-21 instead of ~2^-11.
// ---------------------------------------------------------------------------
template <typename Frag>
__device__ __forceinline__ void split_tf32(Frag& hi, Frag& lo) {
    #pragma unroll
    for (int t = 0; t < hi.num_elements; t++) {
        float a = hi.x[t];
        float h = wmma::__float_to_tf32(a);
        hi.x[t] = h;
        lo.x[t] = wmma::__float_to_tf32(a - h);
    }
}

// ---------------------------------------------------------------------------
// TF32(3x) GEMM: C[4096,1024] = A[4096,1024] @ W[1024,1024] (+ epilogue)
// fused==1: one launch computes Q,K,V (blockIdx.z = 0/1/2 selects W/bias/out,
//           epilogue does bias + elementwise-rope (+0.125 for Q)).
// fused==0: out-projection g_ao @ Wo -> Cout, plain epilogue.
// Block tile 128x64, K-tile 32, 2-stage cp.async pipeline.
// 256 threads (8 warps, 4x2 warp grid, each warp 32x32 of C).
// Dynamic smem: 2 stages x (128x40 A + 32x72 B) floats = 59392 B.
// ---------------------------------------------------------------------------
#define GEMM_SMEM_BYTES 59392
#define STG_FLOATS (128*40 + 32*72)   // 7424 floats per stage

__global__ __launch_bounds__(256)
void gemm_kernel(const float* __restrict__ Ain,
                 const float* __restrict__ W0,
                 const float* __restrict__ W1,
                 const float* __restrict__ W2,
                 const float* __restrict__ b0,
                 const float* __restrict__ b1,
                 const float* __restrict__ b2,
                 const float* __restrict__ sinus,
                 float* __restrict__ Cout,
                 int fused)
{
    extern __shared__ float sbuf[];
    float* Cs = sbuf;                          // 128 x 64 staging (epilogue)

    const int z = blockIdx.z;                  // 0=Q 1=K 2=V (fused), 0 (out-proj)
    const float* A    = fused ? Ain : g_ao;
    const float* W    = fused ? (z == 0 ? W0 : z == 1 ? W1 : W2) : W0;
    const float* bias = fused ? (z == 0 ? b0 : z == 1 ? b1 : b2) : nullptr;
    float*       C    = fused ? (z == 0 ? g_q : z == 1 ? g_k : g_v) : Cout;

    const int tid = threadIdx.x;
    const int wid = tid >> 5;
    const int wm  = wid & 3;        // warp row (4)
    const int wn  = wid >> 2;       // warp col (2)
    const int m0  = blockIdx.y * 128;
    const int n0  = blockIdx.x * 64;

    // Per-thread load coordinates (fixed across tiles)
    const int ar  = (tid >> 3);          // A: 8 float4 per 32-col row
    const int ac4 = (tid & 7) << 2;
    const int br  = (tid >> 4);          // B: 16 float4 per 64-col row
    const int bc4 = (tid & 15) << 2;

    wmma::fragment<wmma::accumulator, 16, 16, 8, float> acc[2][2];
    #pragma unroll
    for (int i = 0; i < 2; i++)
        #pragma unroll
        for (int j = 0; j < 2; j++)
            wmma::fill_fragment(acc[i][j], 0.0f);

    // ---- async tile loader: tile kt -> stage s ----
    auto load_tile = [&](int kt, int s) {
        float* As = sbuf + s*STG_FLOATS;
        float* Bs = As + 128*40;
        const float* ap = &A[(size_t)(m0)*HIDN + kt*32];
        #pragma unroll
        for (int i = 0; i < 4; i++) {
            int r = ar + i*32;
            cpa16(&As[r*40 + ac4], &ap[(size_t)r*HIDN + ac4]);
        }
        const float* bp = &W[(size_t)(kt*32)*HIDN + n0];
        #pragma unroll
        for (int i = 0; i < 2; i++) {
            int r = br + i*16;
            cpa16(&Bs[r*72 + bc4], &bp[(size_t)r*HIDN + bc4]);
        }
        cpa_commit();
    };

    const int NKT = HIDN/32;   // 32
    load_tile(0, 0);

    for (int kt = 0; kt < NKT; kt++) {
        if (kt + 1 < NKT) {
            load_tile(kt + 1, (kt + 1) & 1);
            cpa_wait<1>();
        } else {
            cpa_wait<0>();
        }
        __syncthreads();

        float* As = sbuf + (kt & 1)*STG_FLOATS;
        float* Bs = As + 128*40;

        #pragma unroll
        for (int kk = 0; kk < 4; kk++) {
            wmma::fragment<wmma::matrix_a, 16, 16, 8, wmma::precision::tf32, wmma::row_major> ah[2], al[2];
            wmma::fragment<wmma::matrix_b, 16, 16, 8, wmma::precision::tf32, wmma::row_major> bh[2], bl[2];
            #pragma unroll
            for (int i = 0; i < 2; i++) {
                wmma::load_matrix_sync(ah[i], &As[(wm*32 + i*16)*40 + kk*8], 40);
                split_tf32(ah[i], al[i]);
            }
            #pragma unroll
            for (int j = 0; j < 2; j++) {
                wmma::load_matrix_sync(bh[j], &Bs[kk*8*72 + wn*32 + j*16], 72);
                split_tf32(bh[j], bl[j]);
            }
            #pragma unroll
            for (int i = 0; i < 2; i++)
                #pragma unroll
                for (int j = 0; j < 2; j++) {
                    wmma::mma_sync(acc[i][j], al[i], bh[j], acc[i][j]);
                    wmma::mma_sync(acc[i][j], ah[i], bl[j], acc[i][j]);
                    wmma::mma_sync(acc[i][j], ah[i], bh[j], acc[i][j]);
                }
        }
        __syncthreads();   // stage (kt&1) free for reuse at iteration kt+1's issue
    }

    // Stage C to smem for elementwise epilogue (all compute barriered above;
    // no cp.async pending into stage 0: last load went to stage 1).
    #pragma unroll
    for (int i = 0; i < 2; i++)
        #pragma unroll
        for (int j = 0; j < 2; j++)
            wmma::store_matrix_sync(&Cs[(wm*32 + i*16)*64 + wn*32 + j*16],
                                    acc[i][j], 64, wmma::mem_row_major);
    __syncthreads();

    // Epilogue: bias + rope(elementwise!) + scale, write [token, hid]
    #pragma unroll 8
    for (int it = 0; it < 32; it++) {
        int lin = tid + it*256;
        int r = lin >> 6;
        int c = lin & 63;
        int row = m0 + r;             // token index
        int col = n0 + c;             // hid index
        float v = Cs[r*64 + c];
        if (fused) {
            v += bias[col];
            int d = col & (HD - 1);
            if (z < 2 && d < ROTD) {
                int b = row >> 11;            // /SQ
                int s = row & (SQ - 1);
                float sn = sinus[((b*2 + 0)*SQ + s)*ROTD + d];
                float cs = sinus[((b*2 + 1)*SQ + s)*ROTD + d];
                // reference "rotary" is elementwise: rt[2i]=-r[2i], rt[2i+1]=r[2i+1]
                v = v * (cs + ((d & 1) ? sn : -sn));
            }
            if (z == 0) v *= 0.125f;          // 1/sqrt(D)
        }
        C[(size_t)row*HIDN + col] = v;
    }
}

// ---------------------------------------------------------------------------
// Flash attention: one CTA per (b, h, 64-query tile). K/V tiles of 64.
// S = Q K^T and PV via 3xTF32 wmma; online softmax in regs (4-lane shfl).
// 2-stage cp.async prefetch of K/V. PV output is staged into the CURRENT
// stage's K buffer (dead after the S-mma; post-S barrier orders the reuse).
// Dynamic smem: 6 buffers of 64x72 floats = 110592 B -> 2 CTAs/SM (216 KB).
// ---------------------------------------------------------------------------
#define ATT_BUF   (64*72)              // 4608 floats per buffer
#define ATT_SMEM_BYTES (6*ATT_BUF*4)   // 110592 B

__global__ __launch_bounds__(256, 2)
void attn_kernel(const float* __restrict__ abias)
{
    extern __shared__ float smem[];
    float* Qs = smem;                              // 64x72
    // K/V stages: stage s -> Ks = smem + (1 + 2s)*ATT_BUF, Vs = Ks + ATT_BUF
    float* Ss = smem + 5*ATT_BUF;                  // scores, then P (in place)

    const int tid = threadIdx.x;
    const int wid = tid >> 5;
    const int wm  = wid & 3;           // warp row tile (16 rows)
    const int wn  = wid >> 2;          // warp col tile (32 cols)

    const int bh = blockIdx.y;
    const int b  = bh >> 4;
    const int h  = bh & 15;
    const int q0 = blockIdx.x * 64;

    // K/V async tile loader: tile kt -> stage s (one commit group)
    auto load_kv = [&](int kt, int s) {
        float* Ks = smem + (1 + 2*s)*ATT_BUF;
        float* Vs = Ks + ATT_BUF;
        const int k0 = kt * 64;
        const float* kp = g_k + ((size_t)(b*SQ + k0))*HIDN + h*HD;
        const float* vp = g_v + ((size_t)(b*SQ + k0))*HIDN + h*HD;
        #pragma unroll
        for (int i = 0; i < 4; i++) {
            int lin = tid + i*256;
            int rr = lin >> 4;
            int c4 = (lin & 15) << 2;
            cpa16(&Ks[rr*72 + c4], &kp[(size_t)rr*HIDN + c4]);
            cpa16(&Vs[rr*72 + c4], &vp[(size_t)rr*HIDN + c4]);
        }
        cpa_commit();
    };

    load_kv(0, 0);   // prefetch first K/V tile ASAP

    // Load Q tile (64x64 -> 1024 float4, 4 per thread)
    {
        const float* qp = g_q + ((size_t)(b*SQ + q0))*HIDN + h*HD;
        #pragma unroll
        for (int i = 0; i < 4; i++) {
            int lin = tid + i*256;
            int r  = lin >> 4;
            int c4 = (lin & 15) << 2;
            *(float4*)&Qs[r*72 + c4] = *(const float4*)&qp[(size_t)r*HIDN + c4];
        }
    }

    // Per-thread softmax state: row r, 16-col segment
    const int r    = tid >> 2;
    const int cseg = (tid & 3) << 4;
    float mrun = -1e30f, lrun = 0.0f;
    float o[16];
    #pragma unroll
    for (int j = 0; j < 16; j++) o[j] = 0.0f;

    const size_t bias_row = (size_t)b*SQ*SQ + (size_t)(q0 + r)*SQ;
    const int NT = SQ/64;   // 32

    for (int kt = 0; kt < NT; kt++) {
        const int k0 = kt * 64;
        const int s  = kt & 1;
        float* Ks = smem + (1 + 2*s)*ATT_BUF;
        float* Vs = Ks + ATT_BUF;
        float* PVs = Ks;                    // K(s) dead after S-mma; reuse for PV

        // Prefetch next tile into the other stage; wait for current stage.
        if (kt + 1 < NT) {
            load_kv(kt + 1, s ^ 1);
            cpa_wait<1>();
        } else {
            cpa_wait<0>();
        }
        __syncthreads();   // current-stage K/V visible (also covers Q on kt==0,
                           // and prior iter's PVs reads before PV-buffer reuse)

        // S = Q K^T  (64x64x64, 3xTF32); warp: rows wm*16, cols wn*32 (2 tiles)
        {
            wmma::fragment<wmma::accumulator, 16, 16, 8, float> sa[2];
            wmma::fill_fragment(sa[0], 0.0f);
            wmma::fill_fragment(sa[1], 0.0f);
            #pragma unroll
            for (int kk = 0; kk < 8; kk++) {
                wmma::fragment<wmma::matrix_a, 16, 16, 8, wmma::precision::tf32, wmma::row_major> ah, al;
                wmma::load_matrix_sync(ah, &Qs[(wm*16)*72 + kk*8], 72);
                split_tf32(ah, al);
                #pragma unroll
                for (int j = 0; j < 2; j++) {
                    wmma::fragment<wmma::matrix_b, 16, 16, 8, wmma::precision::tf32, wmma::col_major> bh, bl;
                    wmma::load_matrix_sync(bh, &Ks[(wn*32 + j*16)*72 + kk*8], 72);
                    split_tf32(bh, bl);
                    wmma::mma_sync(sa[j], al, bh, sa[j]);
                    wmma::mma_sync(sa[j], ah, bl, sa[j]);
                    wmma::mma_sync(sa[j], ah, bh, sa[j]);
                }
            }
            #pragma unroll
            for (int j = 0; j < 2; j++)
                wmma::store_matrix_sync(&Ss[(wm*16)*72 + wn*32 + j*16], sa[j], 72,
                                        wmma::mem_row_major);
        }
        __syncthreads();   // Ss ready; all Ks reads done (PVs reuse safe)

        // Online softmax over this key tile (thread owns row r, cols cseg..+15)
        {
            float sv[16];
            #pragma unroll
            for (int j4 = 0; j4 < 4; j4++) {
                float4 bb = *(const float4*)&abias[bias_row + k0 + cseg + j4*4];
                sv[j4*4+0] = Ss[r*72 + cseg + j4*4 + 0] + bb.x;
                sv[j4*4+1] = Ss[r*72 + cseg + j4*4 + 1] + bb.y;
                sv[j4*4+2] = Ss[r*72 + cseg + j4*4 + 2] + bb.z;
                sv[j4*4+3] = Ss[r*72 + cseg + j4*4 + 3] + bb.w;
            }
            float tmax = sv[0];
            #pragma unroll
            for (int j = 1; j < 16; j++) tmax = fmaxf(tmax, sv[j]);
            tmax = fmaxf(tmax, __shfl_xor_sync(0xffffffffu, tmax, 1));
            tmax = fmaxf(tmax, __shfl_xor_sync(0xffffffffu, tmax, 2));

            float mnew  = fmaxf(mrun, tmax);
            float alpha = __expf(mrun - mnew);
            float tsum = 0.0f;
            #pragma unroll
            for (int j = 0; j < 16; j++) {
                float p = __expf(sv[j] - mnew);
                tsum += p;
                Ss[r*72 + cseg + j] = p;      // P in place
            }
            tsum += __shfl_xor_sync(0xffffffffu, tsum, 1);
            tsum += __shfl_xor_sync(0xffffffffu, tsum, 2);
            lrun = lrun * alpha + tsum;
            mrun = mnew;
            #pragma unroll
            for (int j = 0; j < 16; j++) o[j] *= alpha;
        }
        __syncthreads();   // P visible to all warps

        // PV = P @ V  (64x64x64, 3xTF32) -> staged into PVs (= current Ks)
        {
            wmma::fragment<wmma::accumulator, 16, 16, 8, float> pv[2];
            wmma::fill_fragment(pv[0], 0.0f);
            wmma::fill_fragment(pv[1], 0.0f);
            #pragma unroll
            for (int kk = 0; kk < 8; kk++) {
                wmma::fragment<wmma::matrix_a, 16, 16, 8, wmma::precision::tf32, wmma::row_major> ah, al;
                wmma::load_matrix_sync(ah, &Ss[(wm*16)*72 + kk*8], 72);
                split_tf32(ah, al);
                #pragma unroll
                for (int j = 0; j < 2; j++) {
                    wmma::fragment<wmma::matrix_b, 16, 16, 8, wmma::precision::tf32, wmma::row_major> bh, bl;
                    wmma::load_matrix_sync(bh, &Vs[(kk*8)*72 + wn*32 + j*16], 72);
                    split_tf32(bh, bl);
                    wmma::mma_sync(pv[j], al, bh, pv[j]);
                    wmma::mma_sync(pv[j], ah, bl, pv[j]);
                    wmma::mma_sync(pv[j], ah, bh, pv[j]);
                }
            }
            #pragma unroll
            for (int j = 0; j < 2; j++)
                wmma::store_matrix_sync(&PVs[(wm*16)*72 + wn*32 + j*16], pv[j], 72,
                                        wmma::mem_row_major);
        }
        __syncthreads();   // PVs ready

        #pragma unroll
        for (int j = 0; j < 16; j++)
            o[j] += PVs[r*72 + cseg + j];
        __syncthreads();   // PVs reads done before next iter reuses/overwrites
    }

    // Normalize and write attention output [token, hid]
    {
        float inv = 1.0f / lrun;
        float* op = g_ao + ((size_t)(b*SQ + q0 + r))*HIDN + h*HD + cseg;
        #pragma unroll
        for (int j = 0; j < 16; j++) op[j] = o[j] * inv;
    }
}

// ---------------------------------------------------------------------------
extern "C" void kernel_launch(void* const* d_in, const int* in_sizes, int n_in,
                              void* d_out, int out_size)
{
    const float* x     = (const float*)d_in[0];
    const float* sinus = (const float*)d_in[1];
    const float* abias = (const float*)d_in[2];
    const float* Wq    = (const float*)d_in[3];
    const float* bq    = (const float*)d_in[4];
    const float* Wk    = (const float*)d_in[5];
    const float* bk    = (const float*)d_in[6];
    const float* Wv    = (const float*)d_in[7];
    const float* bv    = (const float*)d_in[8];
    const float* Wo    = (const float*)d_in[9];
    float* out = (float*)d_out;

    cudaFuncSetAttribute(gemm_kernel,
                         cudaFuncAttributeMaxDynamicSharedMemorySize, GEMM_SMEM_BYTES);
    cudaFuncSetAttribute(attn_kernel,
                         cudaFuncAttributeMaxDynamicSharedMemorySize, ATT_SMEM_BYTES);

    // Fused QKV projection: one launch, z selects Q/K/V (better wave packing)
    dim3 gqkv(HIDN/64, MTOT/128, 3);     // (16, 32, 3) = 1536 CTAs
    gemm_kernel<<<gqkv, 256, GEMM_SMEM_BYTES>>>(x, Wq, Wk, Wv, bq, bk, bv,
                                                sinus, nullptr, 1);

    dim3 ga(SQ/64, NB*NH);               // (32, 32)
    attn_kernel<<<ga, 256, ATT_SMEM_BYTES>>>(abias);

    dim3 go(HIDN/64, MTOT/128, 1);       // out-projection
    gemm_kernel<<<go, 256, GEMM_SMEM_BYTES>>>(nullptr, Wo, nullptr, nullptr,
                                              nullptr, nullptr, nullptr,
                                              nullptr, out, 0);
}

// round 15
// speedup vs baseline: 2.2284x; 2.2284x over previous
#include <cuda_runtime.h>
#include <cuda_bf16.h>
#include <cstdint>
#include <stdint.h>
#include <mma.h>

using namespace nvcuda;
typedef __nv_bfloat16 bf16;

#define HIDN 1024
#define NH   16
#define HD   64
#define ROTD 32
#define NB   2
#define SQ   2048
#define MTOT (NB*SQ)   // 4096 tokens
#define HH   (HIDN*HIDN)

// bf16 hi/lo pair scratch (device globals; no allocation allowed)
__device__ bf16 g_xh[MTOT*HIDN], g_xl[MTOT*HIDN];
__device__ bf16 g_wh[4*HH],      g_wl[4*HH];       // Wq,Wk,Wv,Wo
__device__ bf16 g_qh[MTOT*HIDN], g_ql[MTOT*HIDN];
__device__ bf16 g_kh[MTOT*HIDN], g_kl[MTOT*HIDN];
__device__ bf16 g_vh[MTOT*HIDN], g_vl[MTOT*HIDN];
__device__ bf16 g_aoh[MTOT*HIDN], g_aol[MTOT*HIDN];

// ---------------------------------------------------------------------------
// cp.async helpers (LDGSTS, 16B)
// ---------------------------------------------------------------------------
__device__ __forceinline__ void cpa16(void* smem_dst, const void* gmem_src) {
    unsigned d = (unsigned)__cvta_generic_to_shared(smem_dst);
    asm volatile("cp.async.cg.shared.global [%0], [%1], 16;" :: "r"(d), "l"(gmem_src));
}
__device__ __forceinline__ void cpa_commit() {
    asm volatile("cp.async.commit_group;");
}
template <int N>
__device__ __forceinline__ void cpa_wait() {
    asm volatile("cp.async.wait_group %0;" :: "n"(N));
}

// ---------------------------------------------------------------------------
// fp32 -> bf16 (hi, lo) split:  hi = bf16(v), lo = bf16(v - hi).
// a*b ~= ah*bh + ah*bl + al*bh  (error ~2^-16 per product, fp32 accumulate)
// ---------------------------------------------------------------------------
__global__ void split_kernel(const float* __restrict__ src, int dst_sel,
                             int off, int n)
{
    bf16* h;
    bf16* l;
    if (dst_sel == 0) { h = g_xh;       l = g_xl; }
    else              { h = g_wh + off; l = g_wl + off; }
    int stride = gridDim.x * blockDim.x;
    for (int i = blockIdx.x*blockDim.x + threadIdx.x; i < n; i += stride) {
        float v = src[i];
        bf16 hv = __float2bfloat16(v);
        h[i] = hv;
        l[i] = __float2bfloat16(v - __bfloat162float(hv));
    }
}

// ---------------------------------------------------------------------------
// bf16-pair GEMM: C[4096,1024] = A @ W, 3-term split mma (m16n16k16).
// fused==1: QKV (z=0/1/2), epilogue bias + elementwise-rope (+0.125 Q),
//           output written as bf16 pairs (g_qh/l etc).
// fused==0: out-proj (A=g_ao pair, W=Wo), fp32 output to Cout.
// Block tile 128x64, K-tile 32, 2-stage cp.async pipeline, 8 warps (4x2).
// Stage bytes: AH 128x40 bf16 =10240, AL 10240, BH 32x72 bf16 =4608, BL 4608.
// ---------------------------------------------------------------------------
#define GSTGB 29696
#define GEMM_SMEM_BYTES (2*GSTGB)   // 59392

__global__ __launch_bounds__(256)
void gemm_kernel(const float* __restrict__ b0,
                 const float* __restrict__ b1,
                 const float* __restrict__ b2,
                 const float* __restrict__ sinus,
                 float* __restrict__ Cout,
                 int fused)
{
    extern __shared__ char smem[];

    const int z = blockIdx.z;
    const bf16* Ah = fused ? g_xh : g_aoh;
    const bf16* Al = fused ? g_xl : g_aol;
    const bf16* Wh = g_wh + (size_t)(fused ? z : 3)*HH;
    const bf16* Wl = g_wl + (size_t)(fused ? z : 3)*HH;
    const float* bias = fused ? (z == 0 ? b0 : z == 1 ? b1 : b2) : nullptr;

    const int tid = threadIdx.x;
    const int wid = tid >> 5;
    const int wm  = wid & 3;
    const int wn  = wid >> 2;
    const int m0  = blockIdx.y * 128;
    const int n0  = blockIdx.x * 64;

    wmma::fragment<wmma::accumulator, 16, 16, 16, float> acc[2][2];
    #pragma unroll
    for (int i = 0; i < 2; i++)
        #pragma unroll
        for (int j = 0; j < 2; j++)
            wmma::fill_fragment(acc[i][j], 0.0f);

    // tile kt -> stage s.  A rows: 64B(hi)+64B(lo); B rows: 128B each half.
    auto load_tile = [&](int kt, int s) {
        char* st = smem + s*GSTGB;
        const char* ahp = (const char*)(Ah + (size_t)m0*HIDN + kt*32);
        const char* alp = (const char*)(Al + (size_t)m0*HIDN + kt*32);
        #pragma unroll
        for (int i = 0; i < 2; i++) {
            int id  = tid + i*256;          // 512 chunks per half
            int row = id >> 2;
            int c16 = (id & 3) << 4;
            size_t g = (size_t)row*2048 + c16;
            cpa16(st +         row*80 + c16, ahp + g);
            cpa16(st + 10240 + row*80 + c16, alp + g);
        }
        const char* whp = (const char*)(Wh + (size_t)(kt*32)*HIDN + n0);
        const char* wlp = (const char*)(Wl + (size_t)(kt*32)*HIDN + n0);
        {
            int row = tid >> 3;             // 256 chunks per half
            int c16 = (tid & 7) << 4;
            size_t g = (size_t)row*2048 + c16;
            cpa16(st + 20480 + row*144 + c16, whp + g);
            cpa16(st + 25088 + row*144 + c16, wlp + g);
        }
        cpa_commit();
    };

    const int NKT = HIDN/32;   // 32
    load_tile(0, 0);

    for (int kt = 0; kt < NKT; kt++) {
        if (kt + 1 < NKT) {
            load_tile(kt + 1, (kt + 1) & 1);
            cpa_wait<1>();
        } else {
            cpa_wait<0>();
        }
        __syncthreads();

        char* st = smem + (kt & 1)*GSTGB;
        const bf16* AH = (const bf16*)st;
        const bf16* AL = (const bf16*)(st + 10240);
        const bf16* BH = (const bf16*)(st + 20480);
        const bf16* BL = (const bf16*)(st + 25088);

        #pragma unroll
        for (int kk = 0; kk < 2; kk++) {
            wmma::fragment<wmma::matrix_a, 16, 16, 16, bf16, wmma::row_major> ah[2], al[2];
            wmma::fragment<wmma::matrix_b, 16, 16, 16, bf16, wmma::row_major> bh[2], bl[2];
            #pragma unroll
            for (int i = 0; i < 2; i++) {
                wmma::load_matrix_sync(ah[i], AH + (wm*32 + i*16)*40 + kk*16, 40);
                wmma::load_matrix_sync(al[i], AL + (wm*32 + i*16)*40 + kk*16, 40);
            }
            #pragma unroll
            for (int j = 0; j < 2; j++) {
                wmma::load_matrix_sync(bh[j], BH + (kk*16)*72 + wn*32 + j*16, 72);
                wmma::load_matrix_sync(bl[j], BL + (kk*16)*72 + wn*32 + j*16, 72);
            }
            #pragma unroll
            for (int i = 0; i < 2; i++)
                #pragma unroll
                for (int j = 0; j < 2; j++) {
                    wmma::mma_sync(acc[i][j], al[i], bh[j], acc[i][j]);
                    wmma::mma_sync(acc[i][j], ah[i], bl[j], acc[i][j]);
                    wmma::mma_sync(acc[i][j], ah[i], bh[j], acc[i][j]);
                }
        }
        __syncthreads();
    }

    // Epilogue staging (Cs 32768B overlaps stages; all compute barriered above)
    float* Cs = (float*)smem;
    #pragma unroll
    for (int i = 0; i < 2; i++)
        #pragma unroll
        for (int j = 0; j < 2; j++)
            wmma::store_matrix_sync(&Cs[(wm*32 + i*16)*64 + wn*32 + j*16],
                                    acc[i][j], 64, wmma::mem_row_major);
    __syncthreads();

    bf16* Ch = nullptr; bf16* Cl = nullptr;
    if (fused) {
        Ch = (z == 0) ? g_qh : (z == 1) ? g_kh : g_vh;
        Cl = (z == 0) ? g_ql : (z == 1) ? g_kl : g_vl;
    }
    #pragma unroll 8
    for (int it = 0; it < 32; it++) {
        int lin = tid + it*256;
        int r = lin >> 6;
        int c = lin & 63;
        int row = m0 + r;
        int col = n0 + c;
        float v = Cs[r*64 + c];
        size_t idx = (size_t)row*HIDN + col;
        if (fused) {
            v += bias[col];
            int d = col & (HD - 1);
            if (z < 2 && d < ROTD) {
                int b = row >> 11;
                int s = row & (SQ - 1);
                float sn = sinus[((b*2 + 0)*SQ + s)*ROTD + d];
                float cs = sinus[((b*2 + 1)*SQ + s)*ROTD + d];
                // reference "rotary" is elementwise: rt[2i]=-r[2i], rt[2i+1]=r[2i+1]
                v = v * (cs + ((d & 1) ? sn : -sn));
            }
            if (z == 0) v *= 0.125f;
            bf16 hv = __float2bfloat16(v);
            Ch[idx] = hv;
            Cl[idx] = __float2bfloat16(v - __bfloat162float(hv));
        } else {
            Cout[idx] = v;
        }
    }
}

// ---------------------------------------------------------------------------
// Flash attention, bf16-pair mma. CTA = (b, h, 64-query tile); K/V tiles 64.
// smem bytes: QH 0, QL 9216; stage s: KH 18432+s*36864 (+9216 KL, +18432 VH,
// +27648 VL); S fp32 at 92160 (18432B). P pair stored blocked in S buffer:
// row r, col block cb: [Ph x16 | Pl x16] at r*288 + cb*64 — each thread
// overwrites exactly the bytes of S it read (no extra barrier).
// PV fp32 output overwrites current-stage K pair (dead after S-mma).
// Total 110592 B -> 2 CTAs/SM.
// ---------------------------------------------------------------------------
#define ATT_SMEM_BYTES 110592
#define QL_OFF   9216
#define STG_OFF(s) (18432 + (s)*36864)
#define S_OFF    92160

__global__ __launch_bounds__(256, 2)
void attn_kernel(const float* __restrict__ abias)
{
    extern __shared__ char smem[];

    const int tid = threadIdx.x;
    const int wid = tid >> 5;
    const int wm  = wid & 3;
    const int wn  = wid >> 2;

    const int bh = blockIdx.y;
    const int b  = bh >> 4;
    const int h  = bh & 15;
    const int q0 = blockIdx.x * 64;

    auto load_kv = [&](int kt, int s) {
        char* st = smem + STG_OFF(s);
        size_t base = ((size_t)(b*SQ + kt*64))*HIDN + h*HD;
        const char* kh = (const char*)(g_kh + base);
        const char* kl = (const char*)(g_kl + base);
        const char* vh = (const char*)(g_vh + base);
        const char* vl = (const char*)(g_vl + base);
        #pragma unroll
        for (int i = 0; i < 2; i++) {
            int id  = tid + i*256;          // 512 chunks per buffer
            int row = id >> 3;
            int c16 = (id & 7) << 4;
            size_t g = (size_t)row*2048 + c16;
            int sm = row*144 + c16;
            cpa16(st +         sm, kh + g);
            cpa16(st +  9216 + sm, kl + g);
            cpa16(st + 18432 + sm, vh + g);
            cpa16(st + 27648 + sm, vl + g);
        }
        cpa_commit();
    };

    load_kv(0, 0);   // prefetch first K/V ASAP

    // Q tile pair (plain 16B copies)
    {
        size_t base = ((size_t)(b*SQ + q0))*HIDN + h*HD;
        const char* qh = (const char*)(g_qh + base);
        const char* ql = (const char*)(g_ql + base);
        #pragma unroll
        for (int i = 0; i < 2; i++) {
            int id  = tid + i*256;
            int row = id >> 3;
            int c16 = (id & 7) << 4;
            size_t g = (size_t)row*2048 + c16;
            *(float4*)(smem +          row*144 + c16) = *(const float4*)(qh + g);
            *(float4*)(smem + QL_OFF + row*144 + c16) = *(const float4*)(ql + g);
        }
    }

    const int r    = tid >> 2;
    const int cseg = (tid & 3) << 4;
    float mrun = -1e30f, lrun = 0.0f;
    float o[16];
    #pragma unroll
    for (int j = 0; j < 16; j++) o[j] = 0.0f;

    const size_t bias_row = (size_t)b*SQ*SQ + (size_t)(q0 + r)*SQ;
    const int NT = SQ/64;   // 32

    const bf16* QH = (const bf16*)smem;
    const bf16* QL = (const bf16*)(smem + QL_OFF);
    float* Sf = (float*)(smem + S_OFF);

    for (int kt = 0; kt < NT; kt++) {
        const int k0 = kt * 64;
        const int s  = kt & 1;
        const bf16* KH = (const bf16*)(smem + STG_OFF(s));
        const bf16* KL = (const bf16*)(smem + STG_OFF(s) +  9216);
        const bf16* VH = (const bf16*)(smem + STG_OFF(s) + 18432);
        const bf16* VL = (const bf16*)(smem + STG_OFF(s) + 27648);
        float* PVs = (float*)(smem + STG_OFF(s));   // K pair dead after S-mma

        if (kt + 1 < NT) {
            load_kv(kt + 1, s ^ 1);
            cpa_wait<1>();
        } else {
            cpa_wait<0>();
        }
        __syncthreads();   // stage K/V visible; prior PVs reads done; Q on kt==0

        // S = Q K^T  (64x64x64, bf16 3-term)
        {
            wmma::fragment<wmma::accumulator, 16, 16, 16, float> sa[2];
            wmma::fill_fragment(sa[0], 0.0f);
            wmma::fill_fragment(sa[1], 0.0f);
            #pragma unroll
            for (int kk = 0; kk < 4; kk++) {
                wmma::fragment<wmma::matrix_a, 16, 16, 16, bf16, wmma::row_major> ah, al;
                wmma::load_matrix_sync(ah, QH + (wm*16)*72 + kk*16, 72);
                wmma::load_matrix_sync(al, QL + (wm*16)*72 + kk*16, 72);
                #pragma unroll
                for (int j = 0; j < 2; j++) {
                    wmma::fragment<wmma::matrix_b, 16, 16, 16, bf16, wmma::col_major> bh, bl;
                    wmma::load_matrix_sync(bh, KH + (wn*32 + j*16)*72 + kk*16, 72);
                    wmma::load_matrix_sync(bl, KL + (wn*32 + j*16)*72 + kk*16, 72);
                    wmma::mma_sync(sa[j], al, bh, sa[j]);
                    wmma::mma_sync(sa[j], ah, bl, sa[j]);
                    wmma::mma_sync(sa[j], ah, bh, sa[j]);
                }
            }
            #pragma unroll
            for (int j = 0; j < 2; j++)
                wmma::store_matrix_sync(&Sf[(wm*16)*72 + wn*32 + j*16], sa[j], 72,
                                        wmma::mem_row_major);
        }
        __syncthreads();   // S ready; K reads done (PVs reuse safe)

        // Online softmax; write P as blocked bf16 pair over the bytes read
        {
            float sv[16];
            #pragma unroll
            for (int j4 = 0; j4 < 4; j4++) {
                float4 bb = *(const float4*)&abias[bias_row + k0 + cseg + j4*4];
                sv[j4*4+0] = Sf[r*72 + cseg + j4*4 + 0] + bb.x;
                sv[j4*4+1] = Sf[r*72 + cseg + j4*4 + 1] + bb.y;
                sv[j4*4+2] = Sf[r*72 + cseg + j4*4 + 2] + bb.z;
                sv[j4*4+3] = Sf[r*72 + cseg + j4*4 + 3] + bb.w;
            }
            float tmax = sv[0];
            #pragma unroll
            for (int j = 1; j < 16; j++) tmax = fmaxf(tmax, sv[j]);
            tmax = fmaxf(tmax, __shfl_xor_sync(0xffffffffu, tmax, 1));
            tmax = fmaxf(tmax, __shfl_xor_sync(0xffffffffu, tmax, 2));

            float mnew  = fmaxf(mrun, tmax);
            float alpha = __expf(mrun - mnew);
            float tsum = 0.0f;
            bf16* pp = (bf16*)(smem + S_OFF + r*288 + (cseg >> 4)*64);
            #pragma unroll
            for (int j = 0; j < 16; j++) {
                float p = __expf(sv[j] - mnew);
                tsum += p;
                bf16 hv = __float2bfloat16(p);
                pp[j]      = hv;
                pp[16 + j] = __float2bfloat16(p - __bfloat162float(hv));
            }
            tsum += __shfl_xor_sync(0xffffffffu, tsum, 1);
            tsum += __shfl_xor_sync(0xffffffffu, tsum, 2);
            lrun = lrun * alpha + tsum;
            mrun = mnew;
            #pragma unroll
            for (int j = 0; j < 16; j++) o[j] *= alpha;
        }
        __syncthreads();   // P pair visible

        // PV = P @ V (bf16 3-term) -> PVs (= current K pair region)
        {
            wmma::fragment<wmma::accumulator, 16, 16, 16, float> pv[2];
            wmma::fill_fragment(pv[0], 0.0f);
            wmma::fill_fragment(pv[1], 0.0f);
            const bf16* Pb = (const bf16*)(smem + S_OFF);
            #pragma unroll
            for (int kk = 0; kk < 4; kk++) {
                wmma::fragment<wmma::matrix_a, 16, 16, 16, bf16, wmma::row_major> ph, pl;
                wmma::load_matrix_sync(ph, Pb + (wm*16)*144 + kk*32,      144);
                wmma::load_matrix_sync(pl, Pb + (wm*16)*144 + kk*32 + 16, 144);
                #pragma unroll
                for (int j = 0; j < 2; j++) {
                    wmma::fragment<wmma::matrix_b, 16, 16, 16, bf16, wmma::row_major> vh, vl;
                    wmma::load_matrix_sync(vh, VH + (kk*16)*72 + wn*32 + j*16, 72);
                    wmma::load_matrix_sync(vl, VL + (kk*16)*72 + wn*32 + j*16, 72);
                    wmma::mma_sync(pv[j], pl, vh, pv[j]);
                    wmma::mma_sync(pv[j], ph, vl, pv[j]);
                    wmma::mma_sync(pv[j], ph, vh, pv[j]);
                }
            }
            #pragma unroll
            for (int j = 0; j < 2; j++)
                wmma::store_matrix_sync(&PVs[(wm*16)*72 + wn*32 + j*16], pv[j], 72,
                                        wmma::mem_row_major);
        }
        __syncthreads();   // PVs ready

        #pragma unroll
        for (int j = 0; j < 16; j++)
            o[j] += PVs[r*72 + cseg + j];
        __syncthreads();   // PVs reads done before next iter reuse
    }

    // Normalize; write attention output as bf16 pair
    {
        float inv = 1.0f / lrun;
        size_t base = ((size_t)(b*SQ + q0 + r))*HIDN + h*HD + cseg;
        #pragma unroll
        for (int j = 0; j < 16; j++) {
            float v = o[j] * inv;
            bf16 hv = __float2bfloat16(v);
            g_aoh[base + j] = hv;
            g_aol[base + j] = __float2bfloat16(v - __bfloat162float(hv));
        }
    }
}

// ---------------------------------------------------------------------------
extern "C" void kernel_launch(void* const* d_in, const int* in_sizes, int n_in,
                              void* d_out, int out_size)
{
    const float* x     = (const float*)d_in[0];
    const float* sinus = (const float*)d_in[1];
    const float* abias = (const float*)d_in[2];
    const float* Wq    = (const float*)d_in[3];
    const float* bq    = (const float*)d_in[4];
    const float* Wk    = (const float*)d_in[5];
    const float* bk    = (const float*)d_in[6];
    const float* Wv    = (const float*)d_in[7];
    const float* bv    = (const float*)d_in[8];
    const float* Wo    = (const float*)d_in[9];
    float* out = (float*)d_out;

    cudaFuncSetAttribute(gemm_kernel,
                         cudaFuncAttributeMaxDynamicSharedMemorySize, GEMM_SMEM_BYTES);
    cudaFuncSetAttribute(attn_kernel,
                         cudaFuncAttributeMaxDynamicSharedMemorySize, ATT_SMEM_BYTES);

    // Decompose inputs into bf16 hi/lo pairs
    split_kernel<<<2048, 256>>>(x,  0, 0,    MTOT*HIDN);
    split_kernel<<<1024, 256>>>(Wq, 1, 0,    HH);
    split_kernel<<<1024, 256>>>(Wk, 1, HH,   HH);
    split_kernel<<<1024, 256>>>(Wv, 1, 2*HH, HH);
    split_kernel<<<1024, 256>>>(Wo, 1, 3*HH, HH);

    // Fused QKV projection (z selects Q/K/V)
    dim3 gqkv(HIDN/64, MTOT/128, 3);     // 1536 CTAs
    gemm_kernel<<<gqkv, 256, GEMM_SMEM_BYTES>>>(bq, bk, bv, sinus, nullptr, 1);

    dim3 ga(SQ/64, NB*NH);               // (32, 32)
    attn_kernel<<<ga, 256, ATT_SMEM_BYTES>>>(abias);

    dim3 go(HIDN/64, MTOT/128, 1);       // out-projection
    gemm_kernel<<<go, 256, GEMM_SMEM_BYTES>>>(nullptr, nullptr, nullptr,
                                              nullptr, out, 0);
}